// round 1
// baseline (speedup 1.0000x reference)
#include <cuda_runtime.h>
#include <cuda_bf16.h>

#define NN   100000
#define EE   3200000
#define DIN  512
#define DHID 128
#define DOUT 4

// ---------------- device scratch (static, no allocs) ----------------
__device__ float g_deg [NN];
__device__ float g_dis [NN];
__device__ float g_hs  [(size_t)NN * DHID];   // (X@W1) * dis[row]
__device__ float g_agg1[(size_t)NN * DHID];   // self + neighbor sums (unscaled)
__device__ float g_h1  [(size_t)NN * DHID];   // relu(dis*agg1 + b1)
__device__ float g_hs2 [NN * DOUT];
__device__ float g_agg2[NN * DOUT];
__device__ int   g_is64;

// ---------------- helpers ----------------
__device__ __forceinline__ void red_add_v4(float* p, float4 v) {
    asm volatile("red.global.add.v4.f32 [%0], {%1,%2,%3,%4};"
                 :: "l"(p), "f"(v.x), "f"(v.y), "f"(v.z), "f"(v.w) : "memory");
}
__device__ __forceinline__ void red_add_f(float* p, float v) {
    asm volatile("red.global.add.f32 [%0], %1;" :: "l"(p), "f"(v) : "memory");
}
// edge_index may arrive as int64 (reference dtype) or int32 (JAX x64 off).
__device__ __forceinline__ void load_edge(const void* ei, int e, int& s, int& d) {
    if (g_is64) {
        const long long* p = (const long long*)ei;
        s = (int)p[e];
        d = (int)p[(size_t)EE + e];
    } else {
        const int* p = (const int*)ei;
        s = p[e];
        d = p[EE + e];
    }
}

// ---------------- kernels ----------------

// Detect index width: viewing memory as int32, int64 values < 2^31 have all
// high words == 0. Probability of 32 genuine zero indices in a row ~ 0.
__global__ void detect_kernel(const int* ei32) {
    int all0 = 1;
    #pragma unroll
    for (int i = 1; i < 64; i += 2) all0 &= (ei32[i] == 0);
    g_is64 = all0;
}

__global__ void zero_deg_kernel() {
    int i = blockIdx.x * blockDim.x + threadIdx.x;
    if (i < NN) g_deg[i] = 0.0f;
}

__global__ void degree_kernel(const void* __restrict__ ei) {
    int e = blockIdx.x * blockDim.x + threadIdx.x;
    if (e >= EE) return;
    int s, d;
    load_edge(ei, e, s, d);
    red_add_f(&g_deg[d], 1.0f);
}

__global__ void dis_kernel() {
    int i = blockIdx.x * blockDim.x + threadIdx.x;
    if (i < NN) g_dis[i] = rsqrtf(g_deg[i] + 1.0f);
}

// GEMM1: hs = (X @ W1) * dis[row]; also initializes agg1 with the self term.
// Block tile 64(M) x 128(N), BK=16, 256 threads, TM=8 x TN=4 micro-tile.
__global__ __launch_bounds__(256) void gemm1_kernel(const float* __restrict__ X,
                                                    const float* __restrict__ W1) {
    __shared__ float Xs[16][68];    // [k][m], padded
    __shared__ float Ws[16][128];   // [k][n]

    const int tid  = threadIdx.x;
    const int br   = blockIdx.x * 64;
    const int tcol = (tid & 31) * 4;        // 0..124
    const int trow = (tid >> 5) * 8;        // 0..56

    const int lr   = tid >> 2;              // 0..63  (X load row)
    const int lseg = tid & 3;               // 0..3   (X load k-seg)

    float4 acc[8];
    #pragma unroll
    for (int i = 0; i < 8; i++) acc[i] = make_float4(0.f, 0.f, 0.f, 0.f);

    for (int k0 = 0; k0 < DIN; k0 += 16) {
        __syncthreads();
        // load X tile (64 x 16), transposed into Xs[k][m]
        {
            float4 xv = make_float4(0.f, 0.f, 0.f, 0.f);
            int gr = br + lr;
            if (gr < NN)
                xv = *(const float4*)(X + (size_t)gr * DIN + k0 + lseg * 4);
            Xs[lseg * 4 + 0][lr] = xv.x;
            Xs[lseg * 4 + 1][lr] = xv.y;
            Xs[lseg * 4 + 2][lr] = xv.z;
            Xs[lseg * 4 + 3][lr] = xv.w;
        }
        // load W tile (16 x 128)
        #pragma unroll
        for (int j = 0; j < 2; j++) {
            int idx = tid + j * 256;
            int kk  = idx >> 5;
            int c   = (idx & 31) * 4;
            *(float4*)&Ws[kk][c] =
                *(const float4*)(W1 + (size_t)(k0 + kk) * DHID + c);
        }
        __syncthreads();

        #pragma unroll
        for (int k = 0; k < 16; k++) {
            float4 w = *(float4*)&Ws[k][tcol];
            float xr[8];
            #pragma unroll
            for (int i = 0; i < 8; i++) xr[i] = Xs[k][trow + i];
            #pragma unroll
            for (int i = 0; i < 8; i++) {
                acc[i].x += xr[i] * w.x;
                acc[i].y += xr[i] * w.y;
                acc[i].z += xr[i] * w.z;
                acc[i].w += xr[i] * w.w;
            }
        }
    }

    #pragma unroll
    for (int i = 0; i < 8; i++) {
        int r = br + trow + i;
        if (r < NN) {
            float s = g_dis[r];
            float4 v;
            v.x = acc[i].x * s; v.y = acc[i].y * s;
            v.z = acc[i].z * s; v.w = acc[i].w * s;
            *(float4*)(g_hs   + (size_t)r * DHID + tcol) = v;
            *(float4*)(g_agg1 + (size_t)r * DHID + tcol) = v;  // self term
        }
    }
}

// Edge aggregation layer 1: warp per edge, lane handles one float4 of 128.
__global__ __launch_bounds__(256) void agg1_kernel(const void* __restrict__ ei) {
    int gw   = (blockIdx.x * blockDim.x + threadIdx.x) >> 5;
    int lane = threadIdx.x & 31;
    if (gw >= EE) return;
    int s, d;
    load_edge(ei, gw, s, d);
    float4 v = *((const float4*)(g_hs + (size_t)s * DHID) + lane);
    red_add_v4(g_agg1 + (size_t)d * DHID + lane * 4, v);
}

// h1 = relu(dis * agg1 + b1)
__global__ void relu_kernel(const float* __restrict__ b1) {
    int idx = blockIdx.x * blockDim.x + threadIdx.x;   // over NN*32 float4s
    if (idx >= NN * 32) return;
    int node = idx >> 5;
    int c    = idx & 31;
    float4 a = *((const float4*)g_agg1 + idx);
    float  s = g_dis[node];
    float4 b = *((const float4*)b1 + c);
    float4 v;
    v.x = fmaxf(a.x * s + b.x, 0.f);
    v.y = fmaxf(a.y * s + b.y, 0.f);
    v.z = fmaxf(a.z * s + b.z, 0.f);
    v.w = fmaxf(a.w * s + b.w, 0.f);
    *((float4*)g_h1 + idx) = v;
}

// GEMM2: warp per row; hs2 = (h1 @ W2) * dis; agg2 initialized with self term.
__global__ __launch_bounds__(256) void gemm2_kernel(const float* __restrict__ W2) {
    int gw   = (blockIdx.x * blockDim.x + threadIdx.x) >> 5;
    int lane = threadIdx.x & 31;
    if (gw >= NN) return;
    float4 h  = *((const float4*)(g_h1 + (size_t)gw * DHID) + lane);
    float4 w0 = *(const float4*)(W2 + (4 * lane + 0) * 4);
    float4 w1 = *(const float4*)(W2 + (4 * lane + 1) * 4);
    float4 w2 = *(const float4*)(W2 + (4 * lane + 2) * 4);
    float4 w3 = *(const float4*)(W2 + (4 * lane + 3) * 4);
    float a0 = h.x * w0.x + h.y * w1.x + h.z * w2.x + h.w * w3.x;
    float a1 = h.x * w0.y + h.y * w1.y + h.z * w2.y + h.w * w3.y;
    float a2 = h.x * w0.z + h.y * w1.z + h.z * w2.z + h.w * w3.z;
    float a3 = h.x * w0.w + h.y * w1.w + h.z * w2.w + h.w * w3.w;
    #pragma unroll
    for (int o = 16; o; o >>= 1) {
        a0 += __shfl_xor_sync(0xFFFFFFFFu, a0, o);
        a1 += __shfl_xor_sync(0xFFFFFFFFu, a1, o);
        a2 += __shfl_xor_sync(0xFFFFFFFFu, a2, o);
        a3 += __shfl_xor_sync(0xFFFFFFFFu, a3, o);
    }
    if (lane == 0) {
        float s = g_dis[gw];
        float4 v;
        v.x = a0 * s; v.y = a1 * s; v.z = a2 * s; v.w = a3 * s;
        *((float4*)g_hs2  + gw) = v;
        *((float4*)g_agg2 + gw) = v;  // self term
    }
}

// Edge aggregation layer 2: thread per edge (4 floats).
__global__ void agg2_kernel(const void* __restrict__ ei) {
    int e = blockIdx.x * blockDim.x + threadIdx.x;
    if (e >= EE) return;
    int s, d;
    load_edge(ei, e, s, d);
    float4 v = *((const float4*)g_hs2 + s);
    red_add_v4(g_agg2 + (size_t)d * DOUT, v);
}

// out = dis * agg2 + b2
__global__ void final_kernel(const float* __restrict__ b2, float* __restrict__ out) {
    int i = blockIdx.x * blockDim.x + threadIdx.x;
    if (i >= NN) return;
    float4 a = *((const float4*)g_agg2 + i);
    float  s = g_dis[i];
    float4 b = *(const float4*)b2;
    float4 v;
    v.x = a.x * s + b.x;
    v.y = a.y * s + b.y;
    v.z = a.z * s + b.z;
    v.w = a.w * s + b.w;
    *((float4*)out + i) = v;
}

// ---------------- launch ----------------
extern "C" void kernel_launch(void* const* d_in, const int* in_sizes, int n_in,
                              void* d_out, int out_size) {
    const float* x  = (const float*)d_in[0];
    const void*  ei = d_in[1];
    const float* W1 = (const float*)d_in[2];
    const float* b1 = (const float*)d_in[3];
    const float* W2 = (const float*)d_in[4];
    const float* b2 = (const float*)d_in[5];
    float* out = (float*)d_out;

    detect_kernel<<<1, 1>>>((const int*)ei);
    zero_deg_kernel<<<(NN + 255) / 256, 256>>>();
    degree_kernel<<<(EE + 255) / 256, 256>>>(ei);
    dis_kernel<<<(NN + 255) / 256, 256>>>();
    gemm1_kernel<<<(NN + 63) / 64, 256>>>(x, W1);
    agg1_kernel<<<EE / 8, 256>>>(ei);                 // 3.2M warps, 8 per block
    relu_kernel<<<(NN * 32 + 255) / 256, 256>>>(b1);
    gemm2_kernel<<<(NN + 7) / 8, 256>>>(W2);
    agg2_kernel<<<(EE + 255) / 256, 256>>>(ei);
    final_kernel<<<(NN + 255) / 256, 256>>>(b2, out);
}

// round 3
// speedup vs baseline: 1.8071x; 1.8071x over previous
#include <cuda_runtime.h>
#include <cuda_bf16.h>
#include <cstdint>

#define NN   100000
#define EE   3200000
#define DIN  512
#define DHID 128
#define DOUT 4

// ======================= device scratch (static) =======================
__device__ int   g_degi  [NN];
__device__ float g_dis   [NN];
__device__ int   g_off   [NN];
__device__ int   g_cursor[NN];
__device__ int   g_bsum  [128];
__device__ int   g_boff  [128];
__device__ int   g_esrc  [EE];
__device__ float g_hs    [(size_t)NN * DHID];   // (X@W1) * dis[row]
__device__ float g_hs2   [NN * DOUT];           // (h1@W2) * dis[row]
__device__ __nv_bfloat16 g_wthi[DHID * DIN];    // W1^T hi  [n][k]
__device__ __nv_bfloat16 g_wtlo[DHID * DIN];    // W1^T lo  [n][k]
__device__ int   g_is64;

// edge_index may arrive as int64 (reference dtype) or int32 (JAX x64 off).
__device__ __forceinline__ void load_edge(const void* ei, int e, int& s, int& d) {
    if (g_is64) {
        const long long* p = (const long long*)ei;
        s = (int)p[e];
        d = (int)p[(size_t)EE + e];
    } else {
        const int* p = (const int*)ei;
        s = p[e];
        d = p[EE + e];
    }
}

// ======================= small kernels =======================
__global__ void detect_kernel(const int* ei32) {
    int all0 = 1;
    #pragma unroll
    for (int i = 1; i < 64; i += 2) all0 &= (ei32[i] == 0);
    g_is64 = all0;
}
__global__ void zero_deg_kernel() {
    int i = blockIdx.x * blockDim.x + threadIdx.x;
    if (i < NN) g_degi[i] = 0;
}
__global__ void degree_kernel(const void* __restrict__ ei) {
    int e = blockIdx.x * blockDim.x + threadIdx.x;
    if (e >= EE) return;
    int s, d;
    load_edge(ei, e, s, d);
    atomicAdd(&g_degi[d], 1);
}
__global__ void dis_kernel() {
    int i = blockIdx.x * blockDim.x + threadIdx.x;
    if (i < NN) g_dis[i] = rsqrtf((float)g_degi[i] + 1.0f);
}
// exclusive scan over degrees (3 passes)
__global__ void scan1_kernel() {
    __shared__ int sh[1024];
    int t = threadIdx.x;
    int i = blockIdx.x * 1024 + t;
    int v = (i < NN) ? g_degi[i] : 0;
    sh[t] = v;
    __syncthreads();
    for (int d = 1; d < 1024; d <<= 1) {
        int add = (t >= d) ? sh[t - d] : 0;
        __syncthreads();
        sh[t] += add;
        __syncthreads();
    }
    if (i < NN) g_off[i] = sh[t] - v;          // block-local exclusive
    if (t == 1023) g_bsum[blockIdx.x] = sh[1023];
}
__global__ void scan2_kernel(int nblk) {
    __shared__ int sh[128];
    int t = threadIdx.x;
    int v = (t < nblk) ? g_bsum[t] : 0;
    sh[t] = v;
    __syncthreads();
    for (int d = 1; d < 128; d <<= 1) {
        int add = (t >= d) ? sh[t - d] : 0;
        __syncthreads();
        sh[t] += add;
        __syncthreads();
    }
    if (t < nblk) g_boff[t] = sh[t] - v;       // exclusive
}
__global__ void scan3_kernel() {
    int i = blockIdx.x * blockDim.x + threadIdx.x;
    if (i >= NN) return;
    int o = g_off[i] + g_boff[i >> 10];
    g_off[i] = o;
    g_cursor[i] = o;
}
__global__ void fill_kernel(const void* __restrict__ ei) {
    int e = blockIdx.x * blockDim.x + threadIdx.x;
    if (e >= EE) return;
    int s, d;
    load_edge(ei, e, s, d);
    int pos = atomicAdd(&g_cursor[d], 1);
    g_esrc[pos] = s;
}
// W1 [K][N] -> WT hi/lo bf16 [N][K]
__global__ void wprep_kernel(const float* __restrict__ W1) {
    int idx = blockIdx.x * blockDim.x + threadIdx.x;
    if (idx >= DHID * DIN) return;
    int n = idx >> 9;
    int k = idx & 511;
    float w = W1[(size_t)k * DHID + n];
    __nv_bfloat16 h = __float2bfloat16(w);
    float r = w - __bfloat162float(h);
    g_wthi[idx] = h;
    g_wtlo[idx] = __float2bfloat16(r);
}

// ======================= GEMM1 via mma.sync bf16 (split hi/lo) =======================
// CTA: 128(M) x 128(N), 256 threads = 8 warps as 4(m) x 2(n); warp tile 32 x 64.
// K chunks of 32; per chunk 3 passes: Ahi*Bhi + Alo*Bhi + Ahi*Blo.
// smem pitch 40 bf16 (80B = 20 banks) -> conflict-free quad LDS.32 fragment loads.

#define SPITCH 40

__device__ __forceinline__ void pack_hl(float a, float b, uint32_t& h, uint32_t& l) {
    __nv_bfloat16 ha = __float2bfloat16(a);
    __nv_bfloat16 hb = __float2bfloat16(b);
    __nv_bfloat162 hv; hv.x = ha; hv.y = hb;
    h = *(uint32_t*)&hv;
    __nv_bfloat162 lv;
    lv.x = __float2bfloat16(a - __bfloat162float(ha));
    lv.y = __float2bfloat16(b - __bfloat162float(hb));
    l = *(uint32_t*)&lv;
}

__device__ __forceinline__ void mma_bf16(float* d, const uint32_t* a, const uint32_t* b) {
    asm volatile(
        "mma.sync.aligned.m16n8k16.row.col.f32.bf16.bf16.f32 "
        "{%0,%1,%2,%3}, {%4,%5,%6,%7}, {%8,%9}, {%0,%1,%2,%3};"
        : "+f"(d[0]), "+f"(d[1]), "+f"(d[2]), "+f"(d[3])
        : "r"(a[0]), "r"(a[1]), "r"(a[2]), "r"(a[3]), "r"(b[0]), "r"(b[1]));
}

__global__ void __launch_bounds__(256, 1) gemm1_mma_kernel(const float* __restrict__ X) {
    __shared__ __nv_bfloat16 sAhi[128 * SPITCH];
    __shared__ __nv_bfloat16 sAlo[128 * SPITCH];
    __shared__ __nv_bfloat16 sBhi[128 * SPITCH];
    __shared__ __nv_bfloat16 sBlo[128 * SPITCH];

    const int tid   = threadIdx.x;
    const int lane  = tid & 31;
    const int wid   = tid >> 5;
    const int warpM = wid & 3;          // 0..3 -> m offset *32
    const int warpN = wid >> 2;         // 0..1 -> n offset *64
    const int g     = lane >> 2;        // 0..7
    const int t     = lane & 3;         // 0..3
    const int mbase = blockIdx.x * 128;

    // A staging mapping: thread -> (row ar, k-half ak)
    const int ar = tid >> 1;            // 0..127
    const int ak = (tid & 1) << 4;      // 0 or 16
    const bool av = (mbase + ar) < NN;
    const float* xrow = X + (size_t)(mbase + ar) * DIN;

    float acc[2][8][4];
    #pragma unroll
    for (int mi = 0; mi < 2; mi++)
        #pragma unroll
        for (int ni = 0; ni < 8; ni++)
            #pragma unroll
            for (int q = 0; q < 4; q++) acc[mi][ni][q] = 0.0f;

    for (int kc = 0; kc < DIN / 32; kc++) {
        const int k0 = kc * 32;
        // ---- stage A (convert fp32 -> bf16 hi/lo) ----
        #pragma unroll
        for (int j = 0; j < 4; j++) {
            float4 v = av ? *(const float4*)(xrow + k0 + ak + 4 * j)
                          : make_float4(0.f, 0.f, 0.f, 0.f);
            uint32_t h0, l0, h1, l1;
            pack_hl(v.x, v.y, h0, l0);
            pack_hl(v.z, v.w, h1, l1);
            const int off = ar * SPITCH + ak + 4 * j;
            *(uint32_t*)&sAhi[off]     = h0;
            *(uint32_t*)&sAhi[off + 2] = h1;
            *(uint32_t*)&sAlo[off]     = l0;
            *(uint32_t*)&sAlo[off + 2] = l1;
        }
        // ---- stage B (already bf16 in gmem, hot in L2) ----
        #pragma unroll
        for (int j = 0; j < 2; j++) {
            const int idx = j * 256 + tid;      // 0..511
            const int n   = idx >> 2;
            const int seg = (idx & 3) << 3;     // k offset 0,8,16,24
            uint4 vh = *(const uint4*)(g_wthi + (size_t)n * DIN + k0 + seg);
            uint4 vl = *(const uint4*)(g_wtlo + (size_t)n * DIN + k0 + seg);
            *(uint4*)&sBhi[n * SPITCH + seg] = vh;
            *(uint4*)&sBlo[n * SPITCH + seg] = vl;
        }
        __syncthreads();

        // ---- mma: two k16 halves ----
        #pragma unroll
        for (int kh = 0; kh < 2; kh++) {
            const int kk = kh * 16;
            uint32_t ah[2][4], al[2][4];
            #pragma unroll
            for (int mi = 0; mi < 2; mi++) {
                const int r  = warpM * 32 + mi * 16 + g;
                const int o0 = r * SPITCH + kk + 2 * t;
                const int o1 = (r + 8) * SPITCH + kk + 2 * t;
                ah[mi][0] = *(const uint32_t*)&sAhi[o0];
                ah[mi][1] = *(const uint32_t*)&sAhi[o1];
                ah[mi][2] = *(const uint32_t*)&sAhi[o0 + 8];
                ah[mi][3] = *(const uint32_t*)&sAhi[o1 + 8];
                al[mi][0] = *(const uint32_t*)&sAlo[o0];
                al[mi][1] = *(const uint32_t*)&sAlo[o1];
                al[mi][2] = *(const uint32_t*)&sAlo[o0 + 8];
                al[mi][3] = *(const uint32_t*)&sAlo[o1 + 8];
            }
            uint32_t bh[8][2], bl[8][2];
            #pragma unroll
            for (int ni = 0; ni < 8; ni++) {
                const int n = warpN * 64 + ni * 8 + g;
                const int o = n * SPITCH + kk + 2 * t;
                bh[ni][0] = *(const uint32_t*)&sBhi[o];
                bh[ni][1] = *(const uint32_t*)&sBhi[o + 8];
                bl[ni][0] = *(const uint32_t*)&sBlo[o];
                bl[ni][1] = *(const uint32_t*)&sBlo[o + 8];
            }
            #pragma unroll
            for (int mi = 0; mi < 2; mi++)
                #pragma unroll
                for (int ni = 0; ni < 8; ni++) {
                    mma_bf16(acc[mi][ni], ah[mi], bh[ni]);
                    mma_bf16(acc[mi][ni], al[mi], bh[ni]);
                    mma_bf16(acc[mi][ni], ah[mi], bl[ni]);
                }
        }
        __syncthreads();
    }

    // ---- epilogue: scale by dis, write g_hs ----
    #pragma unroll
    for (int mi = 0; mi < 2; mi++) {
        const int r0 = mbase + warpM * 32 + mi * 16 + g;
        const int r1 = r0 + 8;
        const float s0 = (r0 < NN) ? g_dis[r0] : 0.0f;
        const float s1 = (r1 < NN) ? g_dis[r1] : 0.0f;
        #pragma unroll
        for (int ni = 0; ni < 8; ni++) {
            const int n = warpN * 64 + ni * 8 + 2 * t;
            if (r0 < NN) {
                float2 v; v.x = acc[mi][ni][0] * s0; v.y = acc[mi][ni][1] * s0;
                *(float2*)&g_hs[(size_t)r0 * DHID + n] = v;
            }
            if (r1 < NN) {
                float2 v; v.x = acc[mi][ni][2] * s1; v.y = acc[mi][ni][3] * s1;
                *(float2*)&g_hs[(size_t)r1 * DHID + n] = v;
            }
        }
    }
}

// ======== CSR aggregation layer 1, fused relu + GEMM2 (warp per node) ========
__global__ void __launch_bounds__(256) agg1_fused_kernel(const float* __restrict__ b1,
                                                         const float* __restrict__ W2) {
    int gw   = (blockIdx.x * blockDim.x + threadIdx.x) >> 5;
    int lane = threadIdx.x & 31;
    if (gw >= NN) return;
    int beg = g_off[gw];
    int end = beg + g_degi[gw];
    const float4* hs4 = (const float4*)g_hs;
    float4 acc = hs4[(size_t)gw * 32 + lane];          // self term
    for (int j0 = beg; j0 < end; j0 += 32) {
        int mj = j0 + lane;
        int sj = (mj < end) ? g_esrc[mj] : 0;
        int cnt = min(32, end - j0);
        int u = 0;
        for (; u + 4 <= cnt; u += 4) {
            int s0 = __shfl_sync(0xFFFFFFFFu, sj, u);
            int s1 = __shfl_sync(0xFFFFFFFFu, sj, u + 1);
            int s2 = __shfl_sync(0xFFFFFFFFu, sj, u + 2);
            int s3 = __shfl_sync(0xFFFFFFFFu, sj, u + 3);
            float4 v0 = hs4[(size_t)s0 * 32 + lane];
            float4 v1 = hs4[(size_t)s1 * 32 + lane];
            float4 v2 = hs4[(size_t)s2 * 32 + lane];
            float4 v3 = hs4[(size_t)s3 * 32 + lane];
            acc.x += (v0.x + v1.x) + (v2.x + v3.x);
            acc.y += (v0.y + v1.y) + (v2.y + v3.y);
            acc.z += (v0.z + v1.z) + (v2.z + v3.z);
            acc.w += (v0.w + v1.w) + (v2.w + v3.w);
        }
        for (; u < cnt; u++) {
            int s = __shfl_sync(0xFFFFFFFFu, sj, u);
            float4 v = hs4[(size_t)s * 32 + lane];
            acc.x += v.x; acc.y += v.y; acc.z += v.z; acc.w += v.w;
        }
    }
    // h1 (this lane's 4 features): relu(dis*acc + b1)
    float sc = g_dis[gw];
    float4 b = ((const float4*)b1)[lane];
    float4 h;
    h.x = fmaxf(acc.x * sc + b.x, 0.f);
    h.y = fmaxf(acc.y * sc + b.y, 0.f);
    h.z = fmaxf(acc.z * sc + b.z, 0.f);
    h.w = fmaxf(acc.w * sc + b.w, 0.f);
    // fused GEMM2: out[o] = sum_k h1[k]*W2[k][o], k = 4*lane+0..3
    float4 w0 = *(const float4*)(W2 + (4 * lane + 0) * 4);
    float4 w1 = *(const float4*)(W2 + (4 * lane + 1) * 4);
    float4 w2 = *(const float4*)(W2 + (4 * lane + 2) * 4);
    float4 w3 = *(const float4*)(W2 + (4 * lane + 3) * 4);
    float a0 = h.x * w0.x + h.y * w1.x + h.z * w2.x + h.w * w3.x;
    float a1 = h.x * w0.y + h.y * w1.y + h.z * w2.y + h.w * w3.y;
    float a2 = h.x * w0.z + h.y * w1.z + h.z * w2.z + h.w * w3.z;
    float a3 = h.x * w0.w + h.y * w1.w + h.z * w2.w + h.w * w3.w;
    #pragma unroll
    for (int o = 16; o; o >>= 1) {
        a0 += __shfl_xor_sync(0xFFFFFFFFu, a0, o);
        a1 += __shfl_xor_sync(0xFFFFFFFFu, a1, o);
        a2 += __shfl_xor_sync(0xFFFFFFFFu, a2, o);
        a3 += __shfl_xor_sync(0xFFFFFFFFu, a3, o);
    }
    if (lane == 0) {
        float4 v;
        v.x = a0 * sc; v.y = a1 * sc; v.z = a2 * sc; v.w = a3 * sc;
        *((float4*)g_hs2 + gw) = v;
    }
}

// ======================= CSR aggregation, layer 2 (fused bias) =======================
__global__ void agg2_csr_kernel(const float* __restrict__ b2, float* __restrict__ out) {
    int i = blockIdx.x * blockDim.x + threadIdx.x;
    if (i >= NN) return;
    int beg = g_off[i];
    int end = beg + g_degi[i];
    const float4* h4 = (const float4*)g_hs2;
    float4 acc = h4[i];                                 // self term
    int j = beg;
    for (; j + 4 <= end; j += 4) {
        float4 v0 = h4[g_esrc[j]];
        float4 v1 = h4[g_esrc[j + 1]];
        float4 v2 = h4[g_esrc[j + 2]];
        float4 v3 = h4[g_esrc[j + 3]];
        acc.x += (v0.x + v1.x) + (v2.x + v3.x);
        acc.y += (v0.y + v1.y) + (v2.y + v3.y);
        acc.z += (v0.z + v1.z) + (v2.z + v3.z);
        acc.w += (v0.w + v1.w) + (v2.w + v3.w);
    }
    for (; j < end; j++) {
        float4 v = h4[g_esrc[j]];
        acc.x += v.x; acc.y += v.y; acc.z += v.z; acc.w += v.w;
    }
    float s = g_dis[i];
    float4 b = *(const float4*)b2;
    float4 v;
    v.x = acc.x * s + b.x;
    v.y = acc.y * s + b.y;
    v.z = acc.z * s + b.z;
    v.w = acc.w * s + b.w;
    *((float4*)out + i) = v;
}

// ======================= launch =======================
extern "C" void kernel_launch(void* const* d_in, const int* in_sizes, int n_in,
                              void* d_out, int out_size) {
    const float* x  = (const float*)d_in[0];
    const void*  ei = d_in[1];
    const float* W1 = (const float*)d_in[2];
    const float* b1 = (const float*)d_in[3];
    const float* W2 = (const float*)d_in[4];
    const float* b2 = (const float*)d_in[5];
    float* out = (float*)d_out;

    const int nblk_scan = (NN + 1023) / 1024;           // 98

    detect_kernel<<<1, 1>>>((const int*)ei);
    zero_deg_kernel<<<(NN + 255) / 256, 256>>>();
    degree_kernel<<<(EE + 255) / 256, 256>>>(ei);
    dis_kernel<<<(NN + 255) / 256, 256>>>();
    scan1_kernel<<<nblk_scan, 1024>>>();
    scan2_kernel<<<1, 128>>>(nblk_scan);
    scan3_kernel<<<(NN + 255) / 256, 256>>>();
    fill_kernel<<<(EE + 255) / 256, 256>>>(ei);
    wprep_kernel<<<(DHID * DIN + 255) / 256, 256>>>(W1);
    gemm1_mma_kernel<<<(NN + 127) / 128, 256>>>(x);
    agg1_fused_kernel<<<(NN * 32 + 255) / 256, 256>>>(b1, W2);
    agg2_csr_kernel<<<(NN + 255) / 256, 256>>>(b2, out);
}

// round 4
// speedup vs baseline: 2.2246x; 1.2311x over previous
#include <cuda_runtime.h>
#include <cuda_bf16.h>
#include <cuda_fp16.h>
#include <cstdint>

#define NN   100000
#define EE   3200000
#define DIN  512
#define DHID 128
#define DOUT 4

// ======================= device scratch (static) =======================
__device__ int    g_degi  [NN];
__device__ float  g_dis   [NN];
__device__ int    g_off   [NN];
__device__ int    g_cursor[NN];
__device__ int    g_bsum  [128];
__device__ int    g_boff  [128];
__device__ int    g_esrc  [EE];
__device__ __half g_hsh   [(size_t)NN * DHID];  // (X@W1)*dis, fp16 (gather traffic /2)
__device__ float  g_hs2   [NN * DOUT];          // (h1@W2)*dis
__device__ __nv_bfloat16 g_wthi[DHID * DIN];    // W1^T hi  [n][k]
__device__ __nv_bfloat16 g_wtlo[DHID * DIN];    // W1^T lo  [n][k]
__device__ int    g_is64;

// edge_index may arrive as int64 (reference dtype) or int32 (JAX x64 off).
__device__ __forceinline__ void load_edge(const void* ei, int e, int& s, int& d) {
    if (g_is64) {
        const long long* p = (const long long*)ei;
        s = (int)p[e];
        d = (int)p[(size_t)EE + e];
    } else {
        const int* p = (const int*)ei;
        s = p[e];
        d = p[EE + e];
    }
}

// ======================= small kernels =======================
__global__ void detect_kernel(const int* ei32) {
    int all0 = 1;
    #pragma unroll
    for (int i = 1; i < 64; i += 2) all0 &= (ei32[i] == 0);
    g_is64 = all0;
}
__global__ void zero_deg_kernel() {
    int i = blockIdx.x * blockDim.x + threadIdx.x;
    if (i < NN) g_degi[i] = 0;
}
__global__ void degree_kernel(const void* __restrict__ ei) {
    int e = blockIdx.x * blockDim.x + threadIdx.x;
    if (e >= EE) return;
    int s, d;
    load_edge(ei, e, s, d);
    atomicAdd(&g_degi[d], 1);
}
__global__ void dis_kernel() {
    int i = blockIdx.x * blockDim.x + threadIdx.x;
    if (i < NN) g_dis[i] = rsqrtf((float)g_degi[i] + 1.0f);
}
__global__ void scan1_kernel() {
    __shared__ int sh[1024];
    int t = threadIdx.x;
    int i = blockIdx.x * 1024 + t;
    int v = (i < NN) ? g_degi[i] : 0;
    sh[t] = v;
    __syncthreads();
    for (int d = 1; d < 1024; d <<= 1) {
        int add = (t >= d) ? sh[t - d] : 0;
        __syncthreads();
        sh[t] += add;
        __syncthreads();
    }
    if (i < NN) g_off[i] = sh[t] - v;
    if (t == 1023) g_bsum[blockIdx.x] = sh[1023];
}
__global__ void scan2_kernel(int nblk) {
    __shared__ int sh[128];
    int t = threadIdx.x;
    int v = (t < nblk) ? g_bsum[t] : 0;
    sh[t] = v;
    __syncthreads();
    for (int d = 1; d < 128; d <<= 1) {
        int add = (t >= d) ? sh[t - d] : 0;
        __syncthreads();
        sh[t] += add;
        __syncthreads();
    }
    if (t < nblk) g_boff[t] = sh[t] - v;
}
__global__ void scan3_kernel() {
    int i = blockIdx.x * blockDim.x + threadIdx.x;
    if (i >= NN) return;
    int o = g_off[i] + g_boff[i >> 10];
    g_off[i] = o;
    g_cursor[i] = o;
}
__global__ void fill_kernel(const void* __restrict__ ei) {
    int e = blockIdx.x * blockDim.x + threadIdx.x;
    if (e >= EE) return;
    int s, d;
    load_edge(ei, e, s, d);
    int pos = atomicAdd(&g_cursor[d], 1);
    g_esrc[pos] = s;
}
// W1 [K][N] -> WT hi/lo bf16 [N][K]
__global__ void wprep_kernel(const float* __restrict__ W1) {
    int idx = blockIdx.x * blockDim.x + threadIdx.x;
    if (idx >= DHID * DIN) return;
    int n = idx >> 9;
    int k = idx & 511;
    float w = W1[(size_t)k * DHID + n];
    __nv_bfloat16 h = __float2bfloat16(w);
    float r = w - __bfloat162float(h);
    g_wthi[idx] = h;
    g_wtlo[idx] = __float2bfloat16(r);
}

// ======================= GEMM1 via mma.sync bf16 (split hi/lo) =======================
// CTA: 128(M) x 128(N), 256 threads = 8 warps 4(m) x 2(n); warp tile 32 x 64.
// K chunks of 32; 3 passes per chunk: Ahi*Bhi + Alo*Bhi + Ahi*Blo.
// Register prefetch of next chunk's gmem data hides load latency behind MMA.

#define SPITCH 40

__device__ __forceinline__ void pack_hl(float a, float b, uint32_t& h, uint32_t& l) {
    __nv_bfloat16 ha = __float2bfloat16(a);
    __nv_bfloat16 hb = __float2bfloat16(b);
    __nv_bfloat162 hv; hv.x = ha; hv.y = hb;
    h = *(uint32_t*)&hv;
    __nv_bfloat162 lv;
    lv.x = __float2bfloat16(a - __bfloat162float(ha));
    lv.y = __float2bfloat16(b - __bfloat162float(hb));
    l = *(uint32_t*)&lv;
}

__device__ __forceinline__ void mma_bf16(float* d, const uint32_t* a, const uint32_t* b) {
    asm volatile(
        "mma.sync.aligned.m16n8k16.row.col.f32.bf16.bf16.f32 "
        "{%0,%1,%2,%3}, {%4,%5,%6,%7}, {%8,%9}, {%0,%1,%2,%3};"
        : "+f"(d[0]), "+f"(d[1]), "+f"(d[2]), "+f"(d[3])
        : "r"(a[0]), "r"(a[1]), "r"(a[2]), "r"(a[3]), "r"(b[0]), "r"(b[1]));
}

__global__ void __launch_bounds__(256, 1) gemm1_mma_kernel(const float* __restrict__ X) {
    __shared__ __nv_bfloat16 sAhi[128 * SPITCH];
    __shared__ __nv_bfloat16 sAlo[128 * SPITCH];
    __shared__ __nv_bfloat16 sBhi[128 * SPITCH];
    __shared__ __nv_bfloat16 sBlo[128 * SPITCH];

    const int tid   = threadIdx.x;
    const int lane  = tid & 31;
    const int wid   = tid >> 5;
    const int warpM = wid & 3;
    const int warpN = wid >> 2;
    const int g     = lane >> 2;
    const int t     = lane & 3;
    const int mbase = blockIdx.x * 128;

    // A staging: thread -> (row ar, k-half ak)
    const int ar = tid >> 1;
    const int ak = (tid & 1) << 4;
    const bool av = (mbase + ar) < NN;
    const float* xrow = X + (size_t)(mbase + ar) * DIN;
    // B staging: thread j=0,1 -> (row bn, k-seg bs)
    const int bn0 = tid >> 2;
    const int bn1 = (256 + tid) >> 2;
    const int bs  = (tid & 3) << 3;

    float acc[2][8][4];
    #pragma unroll
    for (int mi = 0; mi < 2; mi++)
        #pragma unroll
        for (int ni = 0; ni < 8; ni++)
            #pragma unroll
            for (int q = 0; q < 4; q++) acc[mi][ni][q] = 0.0f;

    float4 xr[4];
    uint4  bhr[2], blr[2];
    // preload chunk 0
    #pragma unroll
    for (int j = 0; j < 4; j++)
        xr[j] = av ? *(const float4*)(xrow + ak + 4 * j) : make_float4(0.f, 0.f, 0.f, 0.f);
    bhr[0] = *(const uint4*)(g_wthi + (size_t)bn0 * DIN + bs);
    blr[0] = *(const uint4*)(g_wtlo + (size_t)bn0 * DIN + bs);
    bhr[1] = *(const uint4*)(g_wthi + (size_t)bn1 * DIN + bs);
    blr[1] = *(const uint4*)(g_wtlo + (size_t)bn1 * DIN + bs);

    for (int kc = 0; kc < DIN / 32; kc++) {
        // ---- store staged regs to smem ----
        #pragma unroll
        for (int j = 0; j < 4; j++) {
            uint32_t h0, l0, h1, l1;
            pack_hl(xr[j].x, xr[j].y, h0, l0);
            pack_hl(xr[j].z, xr[j].w, h1, l1);
            const int off = ar * SPITCH + ak + 4 * j;
            *(uint32_t*)&sAhi[off]     = h0;
            *(uint32_t*)&sAhi[off + 2] = h1;
            *(uint32_t*)&sAlo[off]     = l0;
            *(uint32_t*)&sAlo[off + 2] = l1;
        }
        *(uint4*)&sBhi[bn0 * SPITCH + bs] = bhr[0];
        *(uint4*)&sBlo[bn0 * SPITCH + bs] = blr[0];
        *(uint4*)&sBhi[bn1 * SPITCH + bs] = bhr[1];
        *(uint4*)&sBlo[bn1 * SPITCH + bs] = blr[1];

        // ---- prefetch next chunk into regs (latency hidden by mma below) ----
        if (kc + 1 < DIN / 32) {
            const int k1 = (kc + 1) * 32;
            #pragma unroll
            for (int j = 0; j < 4; j++)
                xr[j] = av ? *(const float4*)(xrow + k1 + ak + 4 * j)
                           : make_float4(0.f, 0.f, 0.f, 0.f);
            bhr[0] = *(const uint4*)(g_wthi + (size_t)bn0 * DIN + k1 + bs);
            blr[0] = *(const uint4*)(g_wtlo + (size_t)bn0 * DIN + k1 + bs);
            bhr[1] = *(const uint4*)(g_wthi + (size_t)bn1 * DIN + k1 + bs);
            blr[1] = *(const uint4*)(g_wtlo + (size_t)bn1 * DIN + k1 + bs);
        }
        __syncthreads();

        // ---- mma: two k16 halves ----
        #pragma unroll
        for (int kh = 0; kh < 2; kh++) {
            const int kk = kh * 16;
            uint32_t ah[2][4], al[2][4];
            #pragma unroll
            for (int mi = 0; mi < 2; mi++) {
                const int r  = warpM * 32 + mi * 16 + g;
                const int o0 = r * SPITCH + kk + 2 * t;
                const int o1 = (r + 8) * SPITCH + kk + 2 * t;
                ah[mi][0] = *(const uint32_t*)&sAhi[o0];
                ah[mi][1] = *(const uint32_t*)&sAhi[o1];
                ah[mi][2] = *(const uint32_t*)&sAhi[o0 + 8];
                ah[mi][3] = *(const uint32_t*)&sAhi[o1 + 8];
                al[mi][0] = *(const uint32_t*)&sAlo[o0];
                al[mi][1] = *(const uint32_t*)&sAlo[o1];
                al[mi][2] = *(const uint32_t*)&sAlo[o0 + 8];
                al[mi][3] = *(const uint32_t*)&sAlo[o1 + 8];
            }
            uint32_t bh[8][2], bl[8][2];
            #pragma unroll
            for (int ni = 0; ni < 8; ni++) {
                const int n = warpN * 64 + ni * 8 + g;
                const int o = n * SPITCH + kk + 2 * t;
                bh[ni][0] = *(const uint32_t*)&sBhi[o];
                bh[ni][1] = *(const uint32_t*)&sBhi[o + 8];
                bl[ni][0] = *(const uint32_t*)&sBlo[o];
                bl[ni][1] = *(const uint32_t*)&sBlo[o + 8];
            }
            #pragma unroll
            for (int mi = 0; mi < 2; mi++)
                #pragma unroll
                for (int ni = 0; ni < 8; ni++) {
                    mma_bf16(acc[mi][ni], ah[mi], bh[ni]);
                    mma_bf16(acc[mi][ni], al[mi], bh[ni]);
                    mma_bf16(acc[mi][ni], ah[mi], bl[ni]);
                }
        }
        __syncthreads();
    }

    // ---- epilogue: scale by dis, write g_hsh (fp16) ----
    #pragma unroll
    for (int mi = 0; mi < 2; mi++) {
        const int r0 = mbase + warpM * 32 + mi * 16 + g;
        const int r1 = r0 + 8;
        const float s0 = (r0 < NN) ? g_dis[r0] : 0.0f;
        const float s1 = (r1 < NN) ? g_dis[r1] : 0.0f;
        #pragma unroll
        for (int ni = 0; ni < 8; ni++) {
            const int n = warpN * 64 + ni * 8 + 2 * t;
            if (r0 < NN) {
                __half2 v = __floats2half2_rn(acc[mi][ni][0] * s0, acc[mi][ni][1] * s0);
                *(__half2*)&g_hsh[(size_t)r0 * DHID + n] = v;
            }
            if (r1 < NN) {
                __half2 v = __floats2half2_rn(acc[mi][ni][2] * s1, acc[mi][ni][3] * s1);
                *(__half2*)&g_hsh[(size_t)r1 * DHID + n] = v;
            }
        }
    }
}

// ======== CSR aggregation layer 1 (fp16 gather) + relu + fused GEMM2 ========
__global__ void __launch_bounds__(256) agg1_fused_kernel(const float* __restrict__ b1,
                                                         const float* __restrict__ W2) {
    int gw   = (blockIdx.x * blockDim.x + threadIdx.x) >> 5;
    int lane = threadIdx.x & 31;
    if (gw >= NN) return;
    int beg = g_off[gw];
    int end = beg + g_degi[gw];
    const uint2* hs = (const uint2*)g_hsh;    // 4 halves per lane, 32 lanes = 128

    float4 acc;
    {
        uint2 u = hs[(size_t)gw * 32 + lane]; // self term
        float2 p0 = __half22float2(*(__half2*)&u.x);
        float2 p1 = __half22float2(*(__half2*)&u.y);
        acc.x = p0.x; acc.y = p0.y; acc.z = p1.x; acc.w = p1.y;
    }
    for (int j0 = beg; j0 < end; j0 += 32) {
        int mj = j0 + lane;
        int sj = (mj < end) ? g_esrc[mj] : 0;
        int cnt = min(32, end - j0);
        int u = 0;
        for (; u + 4 <= cnt; u += 4) {
            int s0 = __shfl_sync(0xFFFFFFFFu, sj, u);
            int s1 = __shfl_sync(0xFFFFFFFFu, sj, u + 1);
            int s2 = __shfl_sync(0xFFFFFFFFu, sj, u + 2);
            int s3 = __shfl_sync(0xFFFFFFFFu, sj, u + 3);
            uint2 u0 = hs[(size_t)s0 * 32 + lane];
            uint2 u1 = hs[(size_t)s1 * 32 + lane];
            uint2 u2 = hs[(size_t)s2 * 32 + lane];
            uint2 u3 = hs[(size_t)s3 * 32 + lane];
            float2 a0 = __half22float2(*(__half2*)&u0.x), b0 = __half22float2(*(__half2*)&u0.y);
            float2 a1 = __half22float2(*(__half2*)&u1.x), b1v = __half22float2(*(__half2*)&u1.y);
            float2 a2 = __half22float2(*(__half2*)&u2.x), b2v = __half22float2(*(__half2*)&u2.y);
            float2 a3 = __half22float2(*(__half2*)&u3.x), b3v = __half22float2(*(__half2*)&u3.y);
            acc.x += (a0.x + a1.x) + (a2.x + a3.x);
            acc.y += (a0.y + a1.y) + (a2.y + a3.y);
            acc.z += (b0.x + b1v.x) + (b2v.x + b3v.x);
            acc.w += (b0.y + b1v.y) + (b2v.y + b3v.y);
        }
        for (; u < cnt; u++) {
            int s = __shfl_sync(0xFFFFFFFFu, sj, u);
            uint2 uv = hs[(size_t)s * 32 + lane];
            float2 p0 = __half22float2(*(__half2*)&uv.x);
            float2 p1 = __half22float2(*(__half2*)&uv.y);
            acc.x += p0.x; acc.y += p0.y; acc.z += p1.x; acc.w += p1.y;
        }
    }
    // h1 (this lane's 4 features): relu(dis*acc + b1)
    float sc = g_dis[gw];
    float4 b = ((const float4*)b1)[lane];
    float4 h;
    h.x = fmaxf(acc.x * sc + b.x, 0.f);
    h.y = fmaxf(acc.y * sc + b.y, 0.f);
    h.z = fmaxf(acc.z * sc + b.z, 0.f);
    h.w = fmaxf(acc.w * sc + b.w, 0.f);
    // fused GEMM2: out[o] = sum_k h1[k]*W2[k][o], k = 4*lane+0..3
    float4 w0 = *(const float4*)(W2 + (4 * lane + 0) * 4);
    float4 w1 = *(const float4*)(W2 + (4 * lane + 1) * 4);
    float4 w2 = *(const float4*)(W2 + (4 * lane + 2) * 4);
    float4 w3 = *(const float4*)(W2 + (4 * lane + 3) * 4);
    float a0 = h.x * w0.x + h.y * w1.x + h.z * w2.x + h.w * w3.x;
    float a1 = h.x * w0.y + h.y * w1.y + h.z * w2.y + h.w * w3.y;
    float a2 = h.x * w0.z + h.y * w1.z + h.z * w2.z + h.w * w3.z;
    float a3 = h.x * w0.w + h.y * w1.w + h.z * w2.w + h.w * w3.w;
    #pragma unroll
    for (int o = 16; o; o >>= 1) {
        a0 += __shfl_xor_sync(0xFFFFFFFFu, a0, o);
        a1 += __shfl_xor_sync(0xFFFFFFFFu, a1, o);
        a2 += __shfl_xor_sync(0xFFFFFFFFu, a2, o);
        a3 += __shfl_xor_sync(0xFFFFFFFFu, a3, o);
    }
    if (lane == 0) {
        float4 v;
        v.x = a0 * sc; v.y = a1 * sc; v.z = a2 * sc; v.w = a3 * sc;
        *((float4*)g_hs2 + gw) = v;
    }
}

// ======================= CSR aggregation, layer 2 (fused bias) =======================
__global__ void agg2_csr_kernel(const float* __restrict__ b2, float* __restrict__ out) {
    int i = blockIdx.x * blockDim.x + threadIdx.x;
    if (i >= NN) return;
    int beg = g_off[i];
    int end = beg + g_degi[i];
    const float4* h4 = (const float4*)g_hs2;
    float4 acc = h4[i];                                 // self term
    int j = beg;
    for (; j + 4 <= end; j += 4) {
        float4 v0 = h4[g_esrc[j]];
        float4 v1 = h4[g_esrc[j + 1]];
        float4 v2 = h4[g_esrc[j + 2]];
        float4 v3 = h4[g_esrc[j + 3]];
        acc.x += (v0.x + v1.x) + (v2.x + v3.x);
        acc.y += (v0.y + v1.y) + (v2.y + v3.y);
        acc.z += (v0.z + v1.z) + (v2.z + v3.z);
        acc.w += (v0.w + v1.w) + (v2.w + v3.w);
    }
    for (; j < end; j++) {
        float4 v = h4[g_esrc[j]];
        acc.x += v.x; acc.y += v.y; acc.z += v.z; acc.w += v.w;
    }
    float s = g_dis[i];
    float4 b = *(const float4*)b2;
    float4 v;
    v.x = acc.x * s + b.x;
    v.y = acc.y * s + b.y;
    v.z = acc.z * s + b.z;
    v.w = acc.w * s + b.w;
    *((float4*)out + i) = v;
}

// ======================= launch =======================
extern "C" void kernel_launch(void* const* d_in, const int* in_sizes, int n_in,
                              void* d_out, int out_size) {
    const float* x  = (const float*)d_in[0];
    const void*  ei = d_in[1];
    const float* W1 = (const float*)d_in[2];
    const float* b1 = (const float*)d_in[3];
    const float* W2 = (const float*)d_in[4];
    const float* b2 = (const float*)d_in[5];
    float* out = (float*)d_out;

    const int nblk_scan = (NN + 1023) / 1024;           // 98

    detect_kernel<<<1, 1>>>((const int*)ei);
    zero_deg_kernel<<<(NN + 255) / 256, 256>>>();
    degree_kernel<<<(EE + 255) / 256, 256>>>(ei);
    dis_kernel<<<(NN + 255) / 256, 256>>>();
    scan1_kernel<<<nblk_scan, 1024>>>();
    scan2_kernel<<<1, 128>>>(nblk_scan);
    scan3_kernel<<<(NN + 255) / 256, 256>>>();
    fill_kernel<<<(EE + 255) / 256, 256>>>(ei);
    wprep_kernel<<<(DHID * DIN + 255) / 256, 256>>>(W1);
    gemm1_mma_kernel<<<(NN + 127) / 128, 256>>>(x);
    agg1_fused_kernel<<<(NN * 32 + 255) / 256, 256>>>(b1, W2);
    agg2_csr_kernel<<<(NN + 255) / 256, 256>>>(b2, out);
}

// round 5
// speedup vs baseline: 2.2393x; 1.0066x over previous
#include <cuda_runtime.h>
#include <cuda_bf16.h>
#include <cuda_fp16.h>
#include <cstdint>

#define NN   100000
#define EE   3200000
#define DIN  512
#define DHID 128
#define DOUT 4

// ======================= device scratch (static) =======================
__device__ int    g_degi  [NN];
__device__ float  g_dis   [NN];
__device__ int    g_off   [NN];
__device__ int    g_cursor[NN];
__device__ int    g_bsum  [128];
__device__ int    g_boff  [128];
__device__ int    g_esrc  [EE];
__device__ __half g_hsh   [(size_t)NN * DHID];  // (X@W1)*dis, fp16
__device__ float  g_hs2   [NN * DOUT];          // (h1@W2)*dis
__device__ __nv_bfloat16 g_wthi[DHID * DIN];    // W1^T hi  [n][k]
__device__ __nv_bfloat16 g_wtlo[DHID * DIN];    // W1^T lo  [n][k]
__device__ int    g_is64;

// edge_index may arrive as int64 (reference dtype) or int32 (JAX x64 off).
__device__ __forceinline__ void load_edge(const void* ei, int e, int& s, int& d) {
    if (g_is64) {
        const long long* p = (const long long*)ei;
        s = (int)p[e];
        d = (int)p[(size_t)EE + e];
    } else {
        const int* p = (const int*)ei;
        s = p[e];
        d = p[EE + e];
    }
}

// ============ init: detect idx width + zero degrees + W1 transpose/split ============
__global__ void init_kernel(const int* __restrict__ ei32, const float* __restrict__ W1) {
    int idx = blockIdx.x * blockDim.x + threadIdx.x;
    if (idx == 0) {
        int all0 = 1;
        #pragma unroll
        for (int i = 1; i < 64; i += 2) all0 &= (ei32[i] == 0);
        g_is64 = all0;
    }
    if (idx < NN) g_degi[idx] = 0;
    if (idx < DHID * DIN) {
        int n = idx >> 9;
        int k = idx & 511;
        float w = W1[(size_t)k * DHID + n];
        __nv_bfloat16 h = __float2bfloat16(w);
        g_wthi[idx] = h;
        g_wtlo[idx] = __float2bfloat16(w - __bfloat162float(h));
    }
}

__global__ void degree_kernel(const void* __restrict__ ei) {
    int e = (blockIdx.x * blockDim.x + threadIdx.x) * 2;
    if (e >= EE) return;
    if (g_is64) {
        const long long* p = (const long long*)ei;
        longlong2 v = *(const longlong2*)(p + EE + e);
        atomicAdd(&g_degi[(int)v.x], 1);
        atomicAdd(&g_degi[(int)v.y], 1);
    } else {
        const int* p = (const int*)ei;
        int2 v = *(const int2*)(p + EE + e);
        atomicAdd(&g_degi[v.x], 1);
        atomicAdd(&g_degi[v.y], 1);
    }
}

__global__ void dis_kernel() {
    int i = blockIdx.x * blockDim.x + threadIdx.x;
    if (i < NN) g_dis[i] = rsqrtf((float)g_degi[i] + 1.0f);
}

__global__ void scan1_kernel() {
    __shared__ int sh[1024];
    int t = threadIdx.x;
    int i = blockIdx.x * 1024 + t;
    int v = (i < NN) ? g_degi[i] : 0;
    sh[t] = v;
    __syncthreads();
    for (int d = 1; d < 1024; d <<= 1) {
        int add = (t >= d) ? sh[t - d] : 0;
        __syncthreads();
        sh[t] += add;
        __syncthreads();
    }
    if (i < NN) g_off[i] = sh[t] - v;
    if (t == 1023) g_bsum[blockIdx.x] = sh[1023];
}
__global__ void scan2_kernel(int nblk) {
    __shared__ int sh[128];
    int t = threadIdx.x;
    int v = (t < nblk) ? g_bsum[t] : 0;
    sh[t] = v;
    __syncthreads();
    for (int d = 1; d < 128; d <<= 1) {
        int add = (t >= d) ? sh[t - d] : 0;
        __syncthreads();
        sh[t] += add;
        __syncthreads();
    }
    if (t < nblk) g_boff[t] = sh[t] - v;
}
__global__ void scan3_kernel() {
    int i = blockIdx.x * blockDim.x + threadIdx.x;
    if (i >= NN) return;
    int o = g_off[i] + g_boff[i >> 10];
    g_off[i] = o;
    g_cursor[i] = o;
}
__global__ void fill_kernel(const void* __restrict__ ei) {
    int e = blockIdx.x * blockDim.x + threadIdx.x;
    if (e >= EE) return;
    int s, d;
    load_edge(ei, e, s, d);
    int pos = atomicAdd(&g_cursor[d], 1);
    g_esrc[pos] = s;
}

// ======================= GEMM1 via mma.sync bf16 (split hi/lo) =======================
// CTA: 128(M) x 128(N), 256 threads = 8 warps 4(m) x 2(n); warp tile 32 x 64.
// K chunks of 32; 3 passes per chunk: Ahi*Bhi + Alo*Bhi + Ahi*Blo.

#define SPITCH 40

__device__ __forceinline__ void pack_hl(float a, float b, uint32_t& h, uint32_t& l) {
    __nv_bfloat16 ha = __float2bfloat16(a);
    __nv_bfloat16 hb = __float2bfloat16(b);
    __nv_bfloat162 hv; hv.x = ha; hv.y = hb;
    h = *(uint32_t*)&hv;
    __nv_bfloat162 lv;
    lv.x = __float2bfloat16(a - __bfloat162float(ha));
    lv.y = __float2bfloat16(b - __bfloat162float(hb));
    l = *(uint32_t*)&lv;
}

__device__ __forceinline__ void mma_bf16(float* d, const uint32_t* a, const uint32_t* b) {
    asm volatile(
        "mma.sync.aligned.m16n8k16.row.col.f32.bf16.bf16.f32 "
        "{%0,%1,%2,%3}, {%4,%5,%6,%7}, {%8,%9}, {%0,%1,%2,%3};"
        : "+f"(d[0]), "+f"(d[1]), "+f"(d[2]), "+f"(d[3])
        : "r"(a[0]), "r"(a[1]), "r"(a[2]), "r"(a[3]), "r"(b[0]), "r"(b[1]));
}

__global__ void __launch_bounds__(256, 1) gemm1_mma_kernel(const float* __restrict__ X) {
    __shared__ __nv_bfloat16 sAhi[128 * SPITCH];
    __shared__ __nv_bfloat16 sAlo[128 * SPITCH];
    __shared__ __nv_bfloat16 sBhi[128 * SPITCH];
    __shared__ __nv_bfloat16 sBlo[128 * SPITCH];

    const int tid   = threadIdx.x;
    const int lane  = tid & 31;
    const int wid   = tid >> 5;
    const int warpM = wid & 3;
    const int warpN = wid >> 2;
    const int g     = lane >> 2;
    const int t     = lane & 3;
    const int mbase = blockIdx.x * 128;

    const int ar = tid >> 1;
    const int ak = (tid & 1) << 4;
    const bool av = (mbase + ar) < NN;
    const float* xrow = X + (size_t)(mbase + ar) * DIN;
    const int bn0 = tid >> 2;
    const int bn1 = (256 + tid) >> 2;
    const int bs  = (tid & 3) << 3;

    float acc[2][8][4];
    #pragma unroll
    for (int mi = 0; mi < 2; mi++)
        #pragma unroll
        for (int ni = 0; ni < 8; ni++)
            #pragma unroll
            for (int q = 0; q < 4; q++) acc[mi][ni][q] = 0.0f;

    float4 xr[4];
    uint4  bhr[2], blr[2];
    #pragma unroll
    for (int j = 0; j < 4; j++)
        xr[j] = av ? *(const float4*)(xrow + ak + 4 * j) : make_float4(0.f, 0.f, 0.f, 0.f);
    bhr[0] = *(const uint4*)(g_wthi + (size_t)bn0 * DIN + bs);
    blr[0] = *(const uint4*)(g_wtlo + (size_t)bn0 * DIN + bs);
    bhr[1] = *(const uint4*)(g_wthi + (size_t)bn1 * DIN + bs);
    blr[1] = *(const uint4*)(g_wtlo + (size_t)bn1 * DIN + bs);

    for (int kc = 0; kc < DIN / 32; kc++) {
        #pragma unroll
        for (int j = 0; j < 4; j++) {
            uint32_t h0, l0, h1, l1;
            pack_hl(xr[j].x, xr[j].y, h0, l0);
            pack_hl(xr[j].z, xr[j].w, h1, l1);
            const int off = ar * SPITCH + ak + 4 * j;
            *(uint32_t*)&sAhi[off]     = h0;
            *(uint32_t*)&sAhi[off + 2] = h1;
            *(uint32_t*)&sAlo[off]     = l0;
            *(uint32_t*)&sAlo[off + 2] = l1;
        }
        *(uint4*)&sBhi[bn0 * SPITCH + bs] = bhr[0];
        *(uint4*)&sBlo[bn0 * SPITCH + bs] = blr[0];
        *(uint4*)&sBhi[bn1 * SPITCH + bs] = bhr[1];
        *(uint4*)&sBlo[bn1 * SPITCH + bs] = blr[1];

        if (kc + 1 < DIN / 32) {
            const int k1 = (kc + 1) * 32;
            #pragma unroll
            for (int j = 0; j < 4; j++)
                xr[j] = av ? *(const float4*)(xrow + k1 + ak + 4 * j)
                           : make_float4(0.f, 0.f, 0.f, 0.f);
            bhr[0] = *(const uint4*)(g_wthi + (size_t)bn0 * DIN + k1 + bs);
            blr[0] = *(const uint4*)(g_wtlo + (size_t)bn0 * DIN + k1 + bs);
            bhr[1] = *(const uint4*)(g_wthi + (size_t)bn1 * DIN + k1 + bs);
            blr[1] = *(const uint4*)(g_wtlo + (size_t)bn1 * DIN + k1 + bs);
        }
        __syncthreads();

        #pragma unroll
        for (int kh = 0; kh < 2; kh++) {
            const int kk = kh * 16;
            uint32_t ah[2][4], al[2][4];
            #pragma unroll
            for (int mi = 0; mi < 2; mi++) {
                const int r  = warpM * 32 + mi * 16 + g;
                const int o0 = r * SPITCH + kk + 2 * t;
                const int o1 = (r + 8) * SPITCH + kk + 2 * t;
                ah[mi][0] = *(const uint32_t*)&sAhi[o0];
                ah[mi][1] = *(const uint32_t*)&sAhi[o1];
                ah[mi][2] = *(const uint32_t*)&sAhi[o0 + 8];
                ah[mi][3] = *(const uint32_t*)&sAhi[o1 + 8];
                al[mi][0] = *(const uint32_t*)&sAlo[o0];
                al[mi][1] = *(const uint32_t*)&sAlo[o1];
                al[mi][2] = *(const uint32_t*)&sAlo[o0 + 8];
                al[mi][3] = *(const uint32_t*)&sAlo[o1 + 8];
            }
            uint32_t bh[8][2], bl[8][2];
            #pragma unroll
            for (int ni = 0; ni < 8; ni++) {
                const int n = warpN * 64 + ni * 8 + g;
                const int o = n * SPITCH + kk + 2 * t;
                bh[ni][0] = *(const uint32_t*)&sBhi[o];
                bh[ni][1] = *(const uint32_t*)&sBhi[o + 8];
                bl[ni][0] = *(const uint32_t*)&sBlo[o];
                bl[ni][1] = *(const uint32_t*)&sBlo[o + 8];
            }
            #pragma unroll
            for (int mi = 0; mi < 2; mi++)
                #pragma unroll
                for (int ni = 0; ni < 8; ni++) {
                    mma_bf16(acc[mi][ni], ah[mi], bh[ni]);
                    mma_bf16(acc[mi][ni], al[mi], bh[ni]);
                    mma_bf16(acc[mi][ni], ah[mi], bl[ni]);
                }
        }
        __syncthreads();
    }

    #pragma unroll
    for (int mi = 0; mi < 2; mi++) {
        const int r0 = mbase + warpM * 32 + mi * 16 + g;
        const int r1 = r0 + 8;
        const float s0 = (r0 < NN) ? g_dis[r0] : 0.0f;
        const float s1 = (r1 < NN) ? g_dis[r1] : 0.0f;
        #pragma unroll
        for (int ni = 0; ni < 8; ni++) {
            const int n = warpN * 64 + ni * 8 + 2 * t;
            if (r0 < NN) {
                __half2 v = __floats2half2_rn(acc[mi][ni][0] * s0, acc[mi][ni][1] * s0);
                *(__half2*)&g_hsh[(size_t)r0 * DHID + n] = v;
            }
            if (r1 < NN) {
                __half2 v = __floats2half2_rn(acc[mi][ni][2] * s1, acc[mi][ni][3] * s1);
                *(__half2*)&g_hsh[(size_t)r1 * DHID + n] = v;
            }
        }
    }
}

// ======== CSR aggregation layer 1 (fp16 gather, MLP8) + relu + fused GEMM2 ========
__global__ void __launch_bounds__(256) agg1_fused_kernel(const float* __restrict__ b1,
                                                         const float* __restrict__ W2) {
    int gw   = (blockIdx.x * blockDim.x + threadIdx.x) >> 5;
    int lane = threadIdx.x & 31;
    if (gw >= NN) return;
    int beg = g_off[gw];
    int end = beg + g_degi[gw];
    const uint2* hs = (const uint2*)g_hsh;

    float4 acc;
    {
        uint2 u = hs[(size_t)gw * 32 + lane]; // self term
        float2 p0 = __half22float2(*(__half2*)&u.x);
        float2 p1 = __half22float2(*(__half2*)&u.y);
        acc.x = p0.x; acc.y = p0.y; acc.z = p1.x; acc.w = p1.y;
    }
    for (int j0 = beg; j0 < end; j0 += 32) {
        int mj = j0 + lane;
        int sj = (mj < end) ? g_esrc[mj] : 0;
        int cnt = min(32, end - j0);
        int u = 0;
        for (; u + 8 <= cnt; u += 8) {
            int si[8];
            #pragma unroll
            for (int q = 0; q < 8; q++) si[q] = __shfl_sync(0xFFFFFFFFu, sj, u + q);
            uint2 uv[8];
            #pragma unroll
            for (int q = 0; q < 8; q++) uv[q] = hs[(size_t)si[q] * 32 + lane];
            #pragma unroll
            for (int q = 0; q < 8; q++) {
                float2 p0 = __half22float2(*(__half2*)&uv[q].x);
                float2 p1 = __half22float2(*(__half2*)&uv[q].y);
                acc.x += p0.x; acc.y += p0.y; acc.z += p1.x; acc.w += p1.y;
            }
        }
        for (; u < cnt; u++) {
            int s = __shfl_sync(0xFFFFFFFFu, sj, u);
            uint2 uv = hs[(size_t)s * 32 + lane];
            float2 p0 = __half22float2(*(__half2*)&uv.x);
            float2 p1 = __half22float2(*(__half2*)&uv.y);
            acc.x += p0.x; acc.y += p0.y; acc.z += p1.x; acc.w += p1.y;
        }
    }
    float sc = g_dis[gw];
    float4 b = ((const float4*)b1)[lane];
    float4 h;
    h.x = fmaxf(acc.x * sc + b.x, 0.f);
    h.y = fmaxf(acc.y * sc + b.y, 0.f);
    h.z = fmaxf(acc.z * sc + b.z, 0.f);
    h.w = fmaxf(acc.w * sc + b.w, 0.f);
    float4 w0 = *(const float4*)(W2 + (4 * lane + 0) * 4);
    float4 w1 = *(const float4*)(W2 + (4 * lane + 1) * 4);
    float4 w2 = *(const float4*)(W2 + (4 * lane + 2) * 4);
    float4 w3 = *(const float4*)(W2 + (4 * lane + 3) * 4);
    float a0 = h.x * w0.x + h.y * w1.x + h.z * w2.x + h.w * w3.x;
    float a1 = h.x * w0.y + h.y * w1.y + h.z * w2.y + h.w * w3.y;
    float a2 = h.x * w0.z + h.y * w1.z + h.z * w2.z + h.w * w3.z;
    float a3 = h.x * w0.w + h.y * w1.w + h.z * w2.w + h.w * w3.w;
    #pragma unroll
    for (int o = 16; o; o >>= 1) {
        a0 += __shfl_xor_sync(0xFFFFFFFFu, a0, o);
        a1 += __shfl_xor_sync(0xFFFFFFFFu, a1, o);
        a2 += __shfl_xor_sync(0xFFFFFFFFu, a2, o);
        a3 += __shfl_xor_sync(0xFFFFFFFFu, a3, o);
    }
    if (lane == 0) {
        float4 v;
        v.x = a0 * sc; v.y = a1 * sc; v.z = a2 * sc; v.w = a3 * sc;
        *((float4*)g_hs2 + gw) = v;
    }
}

// ======================= CSR aggregation, layer 2 (fused bias) =======================
__global__ void agg2_csr_kernel(const float* __restrict__ b2, float* __restrict__ out) {
    int i = blockIdx.x * blockDim.x + threadIdx.x;
    if (i >= NN) return;
    int beg = g_off[i];
    int end = beg + g_degi[i];
    const float4* h4 = (const float4*)g_hs2;
    float4 acc = h4[i];
    int j = beg;
    for (; j + 4 <= end; j += 4) {
        float4 v0 = h4[g_esrc[j]];
        float4 v1 = h4[g_esrc[j + 1]];
        float4 v2 = h4[g_esrc[j + 2]];
        float4 v3 = h4[g_esrc[j + 3]];
        acc.x += (v0.x + v1.x) + (v2.x + v3.x);
        acc.y += (v0.y + v1.y) + (v2.y + v3.y);
        acc.z += (v0.z + v1.z) + (v2.z + v3.z);
        acc.w += (v0.w + v1.w) + (v2.w + v3.w);
    }
    for (; j < end; j++) {
        float4 v = h4[g_esrc[j]];
        acc.x += v.x; acc.y += v.y; acc.z += v.z; acc.w += v.w;
    }
    float s = g_dis[i];
    float4 b = *(const float4*)b2;
    float4 v;
    v.x = acc.x * s + b.x;
    v.y = acc.y * s + b.y;
    v.z = acc.z * s + b.z;
    v.w = acc.w * s + b.w;
    *((float4*)out + i) = v;
}

// ======================= launch =======================
extern "C" void kernel_launch(void* const* d_in, const int* in_sizes, int n_in,
                              void* d_out, int out_size) {
    const float* x  = (const float*)d_in[0];
    const void*  ei = d_in[1];
    const float* W1 = (const float*)d_in[2];
    const float* b1 = (const float*)d_in[3];
    const float* W2 = (const float*)d_in[4];
    const float* b2 = (const float*)d_in[5];
    float* out = (float*)d_out;

    const int nblk_scan = (NN + 1023) / 1024;           // 98
    const int nblk_init = (NN + 255) / 256;             // covers NN and DHID*DIN

    // order: gemm1 sits at launch index 3 so the fixed ncu capture slot profiles it
    init_kernel  <<<nblk_init, 256>>>((const int*)ei, W1);
    degree_kernel<<<(EE / 2 + 255) / 256, 256>>>(ei);
    dis_kernel   <<<(NN + 255) / 256, 256>>>();
    gemm1_mma_kernel<<<(NN + 127) / 128, 256>>>(x);
    scan1_kernel <<<nblk_scan, 1024>>>();
    scan2_kernel <<<1, 128>>>(nblk_scan);
    scan3_kernel <<<(NN + 255) / 256, 256>>>();
    fill_kernel  <<<(EE + 255) / 256, 256>>>(ei);
    agg1_fused_kernel<<<(NN * 32 + 255) / 256, 256>>>(b1, W2);
    agg2_csr_kernel  <<<(NN + 255) / 256, 256>>>(b2, out);
}